// round 6
// baseline (speedup 1.0000x reference)
#include <cuda_runtime.h>
#include <cuda_bf16.h>
#include <math.h>
#include <stdint.h>

#define HH 128
#define WW 128
#define CIN 64
#define COUT 64
#define BB 2
#define KT 9
#define HW (HH*WW)

// ---------------- scratch (device globals; no allocation) ----------------
__device__ __align__(16) float g_offy[BB * KT * HW];
__device__ __align__(16) float g_offx[BB * KT * HW];
__device__ __align__(16) float g_mask[BB * KT * HW];
__device__ __align__(16) float g_xT[BB * HW * CIN];            // NHWC
__device__ __align__(16) __nv_bfloat16 g_wh[KT * COUT * CIN];  // [k][o][c] hi (BN folded)
__device__ __align__(16) __nv_bfloat16 g_wl[KT * COUT * CIN];  // lo
__device__ float g_bias2[COUT];

// ---------------- helpers ----------------
__device__ __forceinline__ uint32_t smem_u32(const void* p) {
    uint32_t a;
    asm("{ .reg .u64 t; cvta.to.shared.u64 t, %1; cvt.u32.u64 %0, t; }" : "=r"(a) : "l"(p));
    return a;
}
__device__ __forceinline__ unsigned long long pack2(float lo, float hi) {
    unsigned long long r;
    asm("mov.b64 %0, {%1, %2};" : "=l"(r) : "f"(lo), "f"(hi));
    return r;
}
__device__ __forceinline__ void unpack2(unsigned long long v, float& lo, float& hi) {
    asm("mov.b64 {%0, %1}, %2;" : "=f"(lo), "=f"(hi) : "l"(v));
}
__device__ __forceinline__ unsigned long long fma2(unsigned long long a,
                                                   unsigned long long b,
                                                   unsigned long long c) {
    unsigned long long d;
    asm("fma.rn.f32x2 %0, %1, %2, %3;" : "=l"(d) : "l"(a), "l"(b), "l"(c));
    return d;
}

__device__ __forceinline__ void ldm_x4(uint32_t& r0, uint32_t& r1, uint32_t& r2, uint32_t& r3,
                                       uint32_t addr) {
    asm volatile("ldmatrix.sync.aligned.m8n8.x4.shared.b16 {%0,%1,%2,%3}, [%4];"
        : "=r"(r0), "=r"(r1), "=r"(r2), "=r"(r3) : "r"(addr));
}
__device__ __forceinline__ void ldm_x2(uint32_t& r0, uint32_t& r1, uint32_t addr) {
    asm volatile("ldmatrix.sync.aligned.m8n8.x2.shared.b16 {%0,%1}, [%2];"
        : "=r"(r0), "=r"(r1) : "r"(addr));
}
__device__ __forceinline__ void mma16816(float* d,
                                         uint32_t a0, uint32_t a1, uint32_t a2, uint32_t a3,
                                         uint32_t b0, uint32_t b1) {
    asm volatile(
        "mma.sync.aligned.m16n8k16.row.col.f32.bf16.bf16.f32 "
        "{%0,%1,%2,%3}, {%4,%5,%6,%7}, {%8,%9}, {%0,%1,%2,%3};"
        : "+f"(d[0]), "+f"(d[1]), "+f"(d[2]), "+f"(d[3])
        : "r"(a0), "r"(a1), "r"(a2), "r"(a3), "r"(b0), "r"(b1));
}
__device__ __forceinline__ void cp_async16(uint32_t dst, const void* src) {
    asm volatile(
        "{ .reg .u64 g; cvta.to.global.u64 g, %1;\n\t"
        "cp.async.ca.shared.global [%0], [g], 16; }"
        :: "r"(dst), "l"(src) : "memory");
}
__device__ __forceinline__ void cp_async_wait_all() {
    asm volatile("cp.async.commit_group;\n\tcp.async.wait_group 0;" ::: "memory");
}

// ---------------- prep: fold BN; bf16 hi/lo W [k][o][c] ----------------
__global__ void prep_kernel(const float* __restrict__ weight,
                            const float* __restrict__ bias,
                            const float* __restrict__ gamma,
                            const float* __restrict__ beta,
                            const float* __restrict__ run_mean,
                            const float* __restrict__ run_var) {
    int idx = blockIdx.x * blockDim.x + threadIdx.x;
    if (idx < COUT) {
        float inv = gamma[idx] * rsqrtf(run_var[idx] + 1e-5f);
        g_bias2[idx] = (bias[idx] - run_mean[idx]) * inv + beta[idx];
    }
    if (idx < KT * CIN * COUT) {
        int k = idx >> 12;
        int c = (idx >> 6) & 63;
        int o = idx & 63;
        float inv = gamma[o] * rsqrtf(run_var[o] + 1e-5f);
        float val = weight[(o * CIN + c) * KT + k] * inv;
        __nv_bfloat16 hi = __float2bfloat16_rn(val);
        __nv_bfloat16 lo = __float2bfloat16_rn(val - __bfloat162float(hi));
        g_wh[k * 4096 + o * 64 + c] = hi;
        g_wl[k * 4096 + o * 64 + c] = lo;
    }
}

// ---------------- transpose x: NCHW -> NHWC ----------------
__global__ void transpose_kernel(const float* __restrict__ x) {
    __shared__ float t[32][33];
    int bid = blockIdx.x;
    int ct = bid & 1;
    int pt = (bid >> 1) & 511;
    int b = bid >> 10;
    int c0 = ct * 32, p0 = pt * 32;
    int tid = threadIdx.x;

#pragma unroll
    for (int pass = 0; pass < 4; ++pass) {
        int cl = (tid >> 5) + pass * 8;
        t[cl][tid & 31] = x[(b * CIN + c0 + cl) * HW + p0 + (tid & 31)];
    }
    __syncthreads();
    int p = tid >> 3, cc = tid & 7;
    float4 v = make_float4(t[cc * 4 + 0][p], t[cc * 4 + 1][p],
                           t[cc * 4 + 2][p], t[cc * 4 + 3][p]);
    *(float4*)&g_xT[(b * HW + p0 + p) * CIN + c0 + cc * 4] = v;
}

// ---------------- offset conv: 3x3, 64 -> 27 ch, pad 1 (FFMA2) ----------------
// 128 px per block, 128 threads, grid 256 -> 3 blocks/SM (smem-limited)
__global__ void offset_conv_kernel(const float* __restrict__ x,
                                   const float* __restrict__ w_off,
                                   const float* __restrict__ b_off) {
    extern __shared__ float ws[];   // 576 * 28 floats = 64512 B
    int tid = threadIdx.x;

    for (int i = tid; i < 27 * CIN * 9; i += 128) {
        int oc = i / (CIN * 9);
        int rem = i - oc * (CIN * 9);
        int c = rem / 9;
        int t = rem - c * 9;
        ws[(c * 9 + t) * 28 + oc] = w_off[i];
    }
    for (int i = tid; i < 576; i += 128) ws[i * 28 + 27] = 0.0f;
    __syncthreads();

    int pid = blockIdx.x * 128 + tid;
    int b = pid >> 14;
    int h = (pid >> 7) & 127;
    int w = pid & 127;

    unsigned long long acc2[14];
#pragma unroll
    for (int q = 0; q < 14; ++q) {
        float lo = __ldg(&b_off[2 * q]);
        float hi = (2 * q + 1 < 27) ? __ldg(&b_off[2 * q + 1]) : 0.0f;
        acc2[q] = pack2(lo, hi);
    }

    const float* xb = x + b * (CIN * HW);
    for (int c = 0; c < CIN; ++c) {
        const float* xc = xb + c * HW;
        float xv[9];
#pragma unroll
        for (int ty = 0; ty < 3; ++ty) {
#pragma unroll
            for (int tx = 0; tx < 3; ++tx) {
                int hh = h + ty - 1;
                int www = w + tx - 1;
                bool ok = (hh >= 0) & (hh < HH) & (www >= 0) & (www < WW);
                xv[ty * 3 + tx] = ok ? __ldg(&xc[hh * WW + www]) : 0.0f;
            }
        }
#pragma unroll
        for (int t = 0; t < 9; ++t) {
            unsigned long long vv = pack2(xv[t], xv[t]);
            const ulonglong2* w2 = (const ulonglong2*)&ws[(c * 9 + t) * 28];
#pragma unroll
            for (int q = 0; q < 7; ++q) {
                ulonglong2 wp = w2[q];
                acc2[2 * q + 0] = fma2(vv, wp.x, acc2[2 * q + 0]);
                acc2[2 * q + 1] = fma2(vv, wp.y, acc2[2 * q + 1]);
            }
        }
    }

    float acc[28];
#pragma unroll
    for (int q = 0; q < 14; ++q) unpack2(acc2[q], acc[2 * q], acc[2 * q + 1]);

    int base = (b * KT) * HW + h * WW + w;
#pragma unroll
    for (int k = 0; k < KT; ++k) {
        g_offy[base + k * HW] = acc[2 * k];
        g_offx[base + k * HW] = acc[2 * k + 1];
        float z = acc[18 + k];
        g_mask[base + k * HW] = 1.0f / (1.0f + __expf(-z));
    }
}

// ---------------- main: gather (NHWC) + mma.sync bf16 hi/lo + bias + relu ----------------
// block = 64 px (half row), 128 threads = 4 warps, grid 512.
// GEMM: A = S[px][ch] (m=px), B = W[oc][ch] (k x n col-major), D = [px][oc].
// warp w: px half = (w&1)*32 (2 m-tiles), oc half = (w>>1)*32 (4 n-tiles).
#define PADC 72
#define SM_AHI   0
#define SM_ALO   9216
#define SM_WHI   18432
#define SM_WLO   27648
#define SM_CW    36864
#define SM_CA    46080
#define SM_TOTAL 55296

__global__ void __launch_bounds__(128, 4) dcn_main_kernel(float* __restrict__ out) {
    extern __shared__ char sm[];
    uint32_t smb = smem_u32(sm);
    int tid = threadIdx.x;
    int wid = tid >> 5;
    int lane = tid & 31;

    int blk = blockIdx.x;
    int half = blk & 1;
    int row = (blk >> 1) & 127;
    int b = blk >> 8;
    int col0 = half * 64;

    int pxh = wid & 1;        // px half: px0 = pxh*32
    int och = wid >> 1;       // oc half: oc0 = och*32

    float acc[2][4][4];
#pragma unroll
    for (int mt = 0; mt < 2; ++mt)
#pragma unroll
        for (int nt = 0; nt < 4; ++nt)
#pragma unroll
            for (int i = 0; i < 4; ++i) acc[mt][nt][i] = 0.0f;

    float* cw = (float*)(sm + SM_CW);
    int* ca = (int*)(sm + SM_CA);
    const float4* xq = (const float4*)(g_xT + b * (HW * CIN));

    // ---- precompute coords for ALL 9 taps x 64 px ----
    for (int i = tid; i < KT * 64; i += 128) {
        int k = i >> 6;
        int px = i & 63;
        int wc = col0 + px;
        int off_idx = (b * KT + k) * HW + row * WW + wc;
        float oy = g_offy[off_idx];
        float ox = g_offx[off_idx];
        float m  = g_mask[off_idx];
        float py = (float)(row - 1 + k / 3) + oy;
        float pxx = (float)(wc - 1 + k % 3) + ox;
        float y0f = floorf(py), x0f = floorf(pxx);
        float ly = py - y0f, lx = pxx - x0f;
        int y0 = (int)y0f, x0 = (int)x0f;
        float vy0 = (y0 >= 0 && y0 < HH) ? 1.0f : 0.0f;
        float vy1 = (y0 + 1 >= 0 && y0 + 1 < HH) ? 1.0f : 0.0f;
        float vx0 = (x0 >= 0 && x0 < WW) ? 1.0f : 0.0f;
        float vx1 = (x0 + 1 >= 0 && x0 + 1 < WW) ? 1.0f : 0.0f;
        float4 wv;
        wv.x = (1.0f - ly) * (1.0f - lx) * m * vy0 * vx0;
        wv.y = (1.0f - ly) * lx * m * vy0 * vx1;
        wv.z = ly * (1.0f - lx) * m * vy1 * vx0;
        wv.w = ly * lx * m * vy1 * vx1;
        int yc0 = min(max(y0, 0), HH - 1);
        int yc1 = min(max(y0 + 1, 0), HH - 1);
        int xc0 = min(max(x0, 0), WW - 1);
        int xc1 = min(max(x0 + 1, 0), WW - 1);
        int4 av;
        av.x = (yc0 * WW + xc0) * 16;   // float4-quad index into xT image
        av.y = (yc0 * WW + xc1) * 16;
        av.z = (yc1 * WW + xc0) * 16;
        av.w = (yc1 * WW + xc1) * 16;
        *(float4*)&cw[i * 4] = wv;
        *(int4*)&ca[i * 4] = av;
    }
    __syncthreads();

    // ldmatrix byte offsets
    uint32_t a_off[2];
#pragma unroll
    for (int mt = 0; mt < 2; ++mt)
        a_off[mt] = (uint32_t)((pxh * 32 + mt * 16 + (lane & 15)) * (PADC * 2)
                               + (lane >> 4) * 16);
    int l15 = lane & 15;
    uint32_t b_off[4];
#pragma unroll
    for (int nt = 0; nt < 4; ++nt)
        b_off[nt] = (uint32_t)((och * 32 + nt * 8 + (l15 & 7)) * (PADC * 2)
                               + ((l15 >> 3) & 1) * 16);

#pragma unroll 1
    for (int k = 0; k < KT; ++k) {
        // ---- issue async W tile copy (overlaps with gather below) ----
        {
            const __nv_bfloat16* wh = g_wh + k * 4096;
            const __nv_bfloat16* wl = g_wl + k * 4096;
#pragma unroll
            for (int j = 0; j < 4; ++j) {
                int idx2 = tid + j * 128;        // 0..511 : o = idx2>>3, cc = idx2&7
                int o = idx2 >> 3, cc = idx2 & 7;
                cp_async16(smb + SM_WHI + o * (PADC * 2) + cc * 16, wh + o * 64 + cc * 8);
                cp_async16(smb + SM_WLO + o * (PADC * 2) + cc * 16, wl + o * 64 + cc * 8);
            }
        }

        // ---- gather + hi/lo convert + store S tiles [px][ch] ----
        int q = tid & 15;                 // channel quad (4 ch)
#pragma unroll 1
        for (int r = 0; r < 8; ++r) {
            int px = r * 8 + (tid >> 4);
            int ci = (k * 64 + px) * 4;
            float4 wv = *(const float4*)&cw[ci];
            int4 av = *(const int4*)&ca[ci];
            float4 v00 = xq[av.x + q];
            float4 v01 = xq[av.y + q];
            float4 v10 = xq[av.z + q];
            float4 v11 = xq[av.w + q];
            float4 v;
            v.x = wv.x * v00.x + wv.y * v01.x + wv.z * v10.x + wv.w * v11.x;
            v.y = wv.x * v00.y + wv.y * v01.y + wv.z * v10.y + wv.w * v11.y;
            v.z = wv.x * v00.z + wv.y * v01.z + wv.z * v10.z + wv.w * v11.z;
            v.w = wv.x * v00.w + wv.y * v01.w + wv.z * v10.w + wv.w * v11.w;

            __nv_bfloat16 hx = __float2bfloat16_rn(v.x);
            __nv_bfloat16 hy = __float2bfloat16_rn(v.y);
            __nv_bfloat16 hz = __float2bfloat16_rn(v.z);
            __nv_bfloat16 hw = __float2bfloat16_rn(v.w);
            __nv_bfloat16 lx2 = __float2bfloat16_rn(v.x - __bfloat162float(hx));
            __nv_bfloat16 ly2 = __float2bfloat16_rn(v.y - __bfloat162float(hy));
            __nv_bfloat16 lz2 = __float2bfloat16_rn(v.z - __bfloat162float(hz));
            __nv_bfloat16 lw2 = __float2bfloat16_rn(v.w - __bfloat162float(hw));
            uint2 hi2, lo2;
            hi2.x = (uint32_t)__bfloat16_as_ushort(hx) | ((uint32_t)__bfloat16_as_ushort(hy) << 16);
            hi2.y = (uint32_t)__bfloat16_as_ushort(hz) | ((uint32_t)__bfloat16_as_ushort(hw) << 16);
            lo2.x = (uint32_t)__bfloat16_as_ushort(lx2) | ((uint32_t)__bfloat16_as_ushort(ly2) << 16);
            lo2.y = (uint32_t)__bfloat16_as_ushort(lz2) | ((uint32_t)__bfloat16_as_ushort(lw2) << 16);

            *(uint2*)(sm + SM_AHI + px * (PADC * 2) + q * 8) = hi2;
            *(uint2*)(sm + SM_ALO + px * (PADC * 2) + q * 8) = lo2;
        }
        cp_async_wait_all();
        __syncthreads();

        // ---- mma: 3 passes (Sh*Wh, Sh*Wl, Sl*Wh) x 4 k16-steps ----
#pragma unroll
        for (int pass = 0; pass < 3; ++pass) {
            uint32_t wbase = smb + ((pass == 1) ? SM_WLO : SM_WHI);
            uint32_t sbase = smb + ((pass == 2) ? SM_ALO : SM_AHI);
#pragma unroll
            for (int ks = 0; ks < 4; ++ks) {
                uint32_t a[2][4];
#pragma unroll
                for (int mt = 0; mt < 2; ++mt)
                    ldm_x4(a[mt][0], a[mt][1], a[mt][2], a[mt][3],
                           sbase + a_off[mt] + ks * 32);
                uint32_t bf[4][2];
#pragma unroll
                for (int nt = 0; nt < 4; ++nt)
                    ldm_x2(bf[nt][0], bf[nt][1], wbase + b_off[nt] + ks * 32);
#pragma unroll
                for (int mt = 0; mt < 2; ++mt)
#pragma unroll
                    for (int nt = 0; nt < 4; ++nt)
                        mma16816(acc[mt][nt], a[mt][0], a[mt][1], a[mt][2], a[mt][3],
                                 bf[nt][0], bf[nt][1]);
            }
        }
        __syncthreads();
    }

    // ---- epilogue: bias + relu ----
    int obase = b * COUT * HW + row * WW + col0;
#pragma unroll
    for (int mt = 0; mt < 2; ++mt) {
        int px = pxh * 32 + mt * 16 + (lane >> 2);
#pragma unroll
        for (int nt = 0; nt < 4; ++nt) {
            int oc = och * 32 + nt * 8 + (lane & 3) * 2;
            float b0 = __ldg(&g_bias2[oc]);
            float b1 = __ldg(&g_bias2[oc + 1]);
            out[obase + oc * HW + px]           = fmaxf(acc[mt][nt][0] + b0, 0.0f);
            out[obase + (oc + 1) * HW + px]     = fmaxf(acc[mt][nt][1] + b1, 0.0f);
            out[obase + oc * HW + px + 8]       = fmaxf(acc[mt][nt][2] + b0, 0.0f);
            out[obase + (oc + 1) * HW + px + 8] = fmaxf(acc[mt][nt][3] + b1, 0.0f);
        }
    }
}

// ---------------- launch ----------------
extern "C" void kernel_launch(void* const* d_in, const int* in_sizes, int n_in,
                              void* d_out, int out_size) {
    const float* x        = (const float*)d_in[0];
    const float* w_off    = (const float*)d_in[1];
    const float* b_off    = (const float*)d_in[2];
    const float* weight   = (const float*)d_in[3];
    const float* bias     = (const float*)d_in[4];
    const float* gamma    = (const float*)d_in[5];
    const float* beta     = (const float*)d_in[6];
    const float* run_mean = (const float*)d_in[7];
    const float* run_var  = (const float*)d_in[8];
    float* out = (float*)d_out;

    prep_kernel<<<(KT * CIN * COUT + 255) / 256, 256>>>(weight, bias, gamma, beta,
                                                        run_mean, run_var);

    transpose_kernel<<<BB * 2 * 512, 256>>>(x);

    cudaFuncSetAttribute(offset_conv_kernel,
                         cudaFuncAttributeMaxDynamicSharedMemorySize, 576 * 28 * 4);
    offset_conv_kernel<<<(BB * HW) / 128, 128, 576 * 28 * 4>>>(x, w_off, b_off);

    cudaFuncSetAttribute(dcn_main_kernel,
                         cudaFuncAttributeMaxDynamicSharedMemorySize, SM_TOTAL);
    dcn_main_kernel<<<BB * HH * 2, 128, SM_TOTAL>>>(out);
}

// round 7
// speedup vs baseline: 2.0055x; 2.0055x over previous
#include <cuda_runtime.h>
#include <cuda_bf16.h>
#include <math.h>
#include <stdint.h>

#define HH 128
#define WW 128
#define CIN 64
#define COUT 64
#define BB 2
#define KT 9
#define HW (HH*WW)
#define PADC 72   // padded row length (bf16 elems) -> 144B stride, conflict-free ldmatrix

// ---------------- scratch (device globals; no allocation) ----------------
__device__ __align__(16) float g_offy[BB * KT * HW];
__device__ __align__(16) float g_offx[BB * KT * HW];
__device__ __align__(16) float g_mask[BB * KT * HW];
__device__ __align__(16) float g_xT[BB * HW * CIN];            // NHWC fp32
__device__ __align__(16) __nv_bfloat16 g_xh[BB * HW * CIN];    // NHWC bf16 hi
__device__ __align__(16) __nv_bfloat16 g_xl[BB * HW * CIN];    // NHWC bf16 lo
__device__ __align__(16) __nv_bfloat16 g_wh[KT * COUT * CIN];  // main W [k][o][c] hi (BN folded)
__device__ __align__(16) __nv_bfloat16 g_wl[KT * COUT * CIN];  // lo
__device__ __align__(16) __nv_bfloat16 g_woh[KT * 32 * CIN];   // offset W [k][oc(pad32)][c] hi
__device__ __align__(16) __nv_bfloat16 g_wol[KT * 32 * CIN];   // lo
__device__ float g_bias2[COUT];

// ---------------- helpers ----------------
__device__ __forceinline__ uint32_t smem_u32(const void* p) {
    uint32_t a;
    asm("{ .reg .u64 t; cvta.to.shared.u64 t, %1; cvt.u32.u64 %0, t; }" : "=r"(a) : "l"(p));
    return a;
}
__device__ __forceinline__ void ldm_x4(uint32_t& r0, uint32_t& r1, uint32_t& r2, uint32_t& r3,
                                       uint32_t addr) {
    asm volatile("ldmatrix.sync.aligned.m8n8.x4.shared.b16 {%0,%1,%2,%3}, [%4];"
        : "=r"(r0), "=r"(r1), "=r"(r2), "=r"(r3) : "r"(addr));
}
__device__ __forceinline__ void ldm_x2(uint32_t& r0, uint32_t& r1, uint32_t addr) {
    asm volatile("ldmatrix.sync.aligned.m8n8.x2.shared.b16 {%0,%1}, [%2];"
        : "=r"(r0), "=r"(r1) : "r"(addr));
}
__device__ __forceinline__ void mma16816(float* d,
                                         uint32_t a0, uint32_t a1, uint32_t a2, uint32_t a3,
                                         uint32_t b0, uint32_t b1) {
    asm volatile(
        "mma.sync.aligned.m16n8k16.row.col.f32.bf16.bf16.f32 "
        "{%0,%1,%2,%3}, {%4,%5,%6,%7}, {%8,%9}, {%0,%1,%2,%3};"
        : "+f"(d[0]), "+f"(d[1]), "+f"(d[2]), "+f"(d[3])
        : "r"(a0), "r"(a1), "r"(a2), "r"(a3), "r"(b0), "r"(b1));
}
__device__ __forceinline__ void cp_async16(uint32_t dst, const void* src) {
    asm volatile(
        "{ .reg .u64 g; cvta.to.global.u64 g, %1;\n\t"
        "cp.async.ca.shared.global [%0], [g], 16; }"
        :: "r"(dst), "l"(src) : "memory");
}
__device__ __forceinline__ void cp_async_wait_all() {
    asm volatile("cp.async.commit_group;\n\tcp.async.wait_group 0;" ::: "memory");
}

// ---------------- prep: fold BN; build bf16 hi/lo weight tiles ----------------
__global__ void prep_kernel(const float* __restrict__ weight,
                            const float* __restrict__ bias,
                            const float* __restrict__ gamma,
                            const float* __restrict__ beta,
                            const float* __restrict__ run_mean,
                            const float* __restrict__ run_var,
                            const float* __restrict__ w_off) {
    int idx = blockIdx.x * blockDim.x + threadIdx.x;
    if (idx < COUT) {
        float inv = gamma[idx] * rsqrtf(run_var[idx] + 1e-5f);
        g_bias2[idx] = (bias[idx] - run_mean[idx]) * inv + beta[idx];
    }
    if (idx < KT * CIN * COUT) {
        int k = idx >> 12;
        int c = (idx >> 6) & 63;
        int o = idx & 63;
        float inv = gamma[o] * rsqrtf(run_var[o] + 1e-5f);
        float val = weight[(o * CIN + c) * KT + k] * inv;
        __nv_bfloat16 hi = __float2bfloat16_rn(val);
        __nv_bfloat16 lo = __float2bfloat16_rn(val - __bfloat162float(hi));
        g_wh[k * 4096 + o * 64 + c] = hi;
        g_wl[k * 4096 + o * 64 + c] = lo;
    }
    // offset conv weights: [k][oc pad32][c], w_off layout [27][64][3][3]
    if (idx < KT * 32 * CIN) {
        int k = idx >> 11;            // /2048
        int o = (idx >> 6) & 31;
        int c = idx & 63;
        float val = (o < 27) ? w_off[(o * CIN + c) * KT + k] : 0.0f;
        __nv_bfloat16 hi = __float2bfloat16_rn(val);
        __nv_bfloat16 lo = __float2bfloat16_rn(val - __bfloat162float(hi));
        g_woh[idx] = hi;
        g_wol[idx] = lo;
    }
}

// ---------------- transpose x: NCHW -> NHWC (fp32 + bf16 hi/lo) ----------------
__global__ void transpose_kernel(const float* __restrict__ x) {
    __shared__ float t[32][33];
    int bid = blockIdx.x;
    int ct = bid & 1;
    int pt = (bid >> 1) & 511;
    int b = bid >> 10;
    int c0 = ct * 32, p0 = pt * 32;
    int tid = threadIdx.x;

#pragma unroll
    for (int pass = 0; pass < 4; ++pass) {
        int cl = (tid >> 5) + pass * 8;
        t[cl][tid & 31] = x[(b * CIN + c0 + cl) * HW + p0 + (tid & 31)];
    }
    __syncthreads();
    int p = tid >> 3, cc = tid & 7;
    float4 v = make_float4(t[cc * 4 + 0][p], t[cc * 4 + 1][p],
                           t[cc * 4 + 2][p], t[cc * 4 + 3][p]);
    int base = (b * HW + p0 + p) * CIN + c0 + cc * 4;
    *(float4*)&g_xT[base] = v;

    __nv_bfloat16 hx = __float2bfloat16_rn(v.x);
    __nv_bfloat16 hy = __float2bfloat16_rn(v.y);
    __nv_bfloat16 hz = __float2bfloat16_rn(v.z);
    __nv_bfloat16 hw = __float2bfloat16_rn(v.w);
    __nv_bfloat16 lx = __float2bfloat16_rn(v.x - __bfloat162float(hx));
    __nv_bfloat16 ly = __float2bfloat16_rn(v.y - __bfloat162float(hy));
    __nv_bfloat16 lz = __float2bfloat16_rn(v.z - __bfloat162float(hz));
    __nv_bfloat16 lw = __float2bfloat16_rn(v.w - __bfloat162float(hw));
    uint2 hi2, lo2;
    hi2.x = (uint32_t)__bfloat16_as_ushort(hx) | ((uint32_t)__bfloat16_as_ushort(hy) << 16);
    hi2.y = (uint32_t)__bfloat16_as_ushort(hz) | ((uint32_t)__bfloat16_as_ushort(hw) << 16);
    lo2.x = (uint32_t)__bfloat16_as_ushort(lx) | ((uint32_t)__bfloat16_as_ushort(ly) << 16);
    lo2.y = (uint32_t)__bfloat16_as_ushort(lz) | ((uint32_t)__bfloat16_as_ushort(lw) << 16);
    *(uint2*)&g_xh[base] = hi2;
    *(uint2*)&g_xl[base] = lo2;
}

// ---------------- offset conv as mma GEMM: [128 px] x [32 oc] x K=576 ----------------
// block = one row (128 px), 256 threads = 8 warps (each warp: 16 px x 32 oc).
#define OSM_AHI   0
#define OSM_ALO   18432
#define OSM_WHI   36864
#define OSM_WLO   41472
#define OSM_TOTAL 46080

__global__ void __launch_bounds__(256) offset_mma_kernel(const float* __restrict__ boff) {
    extern __shared__ char sm[];
    uint32_t smb = smem_u32(sm);
    int tid = threadIdx.x;
    int wid = tid >> 5;
    int lane = tid & 31;

    int b = blockIdx.x >> 7;
    int row = blockIdx.x & 127;

    float acc[4][4];
#pragma unroll
    for (int nt = 0; nt < 4; ++nt)
#pragma unroll
        for (int i = 0; i < 4; ++i) acc[nt][i] = 0.0f;

    uint32_t a_off = (uint32_t)((wid * 16 + (lane & 15)) * (PADC * 2) + (lane >> 4) * 16);
    int l15 = lane & 15;
    uint32_t b_offv[4];
#pragma unroll
    for (int nt = 0; nt < 4; ++nt)
        b_offv[nt] = (uint32_t)((nt * 8 + (l15 & 7)) * (PADC * 2) + ((l15 >> 3) & 1) * 16);

#pragma unroll 1
    for (int k = 0; k < KT; ++k) {
        int ty = k / 3, tx = k % 3;
        int rr = row - 1 + ty;
        bool row_ok = (rr >= 0) && (rr < HH);

        // ---- W_off tile (4KB hi + 4KB lo): 256 chunks of 16B each ----
        {
            int o = tid >> 3, cc = tid & 7;
            cp_async16(smb + OSM_WHI + o * (PADC * 2) + cc * 16, g_woh + k * 2048 + o * 64 + cc * 8);
            cp_async16(smb + OSM_WLO + o * (PADC * 2) + cc * 16, g_wol + k * 2048 + o * 64 + cc * 8);
        }
        // ---- A tiles: 128 px rows of 128B (hi & lo), shifted by (rr, tx-1) ----
#pragma unroll
        for (int j = 0; j < 4; ++j) {
            int idx2 = tid + j * 256;          // 0..1023
            int px = idx2 >> 3, cc = idx2 & 7;
            int sc = px - 1 + tx;
            bool ok = row_ok && (sc >= 0) && (sc < WW);
            uint32_t dhi = smb + OSM_AHI + px * (PADC * 2) + cc * 16;
            uint32_t dlo = smb + OSM_ALO + px * (PADC * 2) + cc * 16;
            if (ok) {
                int src = (b * HW + rr * WW + sc) * 64 + cc * 8;
                cp_async16(dhi, g_xh + src);
                cp_async16(dlo, g_xl + src);
            } else {
                uint4 z = make_uint4(0, 0, 0, 0);
                *(uint4*)(sm + OSM_AHI + px * (PADC * 2) + cc * 16) = z;
                *(uint4*)(sm + OSM_ALO + px * (PADC * 2) + cc * 16) = z;
            }
        }
        cp_async_wait_all();
        __syncthreads();

        // ---- mma: 3 passes (Ah*Wh, Ah*Wl, Al*Wh) x 4 k16-steps ----
#pragma unroll
        for (int pass = 0; pass < 3; ++pass) {
            uint32_t wbase = smb + ((pass == 1) ? OSM_WLO : OSM_WHI);
            uint32_t sbase = smb + ((pass == 2) ? OSM_ALO : OSM_AHI);
#pragma unroll
            for (int ks = 0; ks < 4; ++ks) {
                uint32_t a0, a1, a2, a3;
                ldm_x4(a0, a1, a2, a3, sbase + a_off + ks * 32);
#pragma unroll
                for (int nt = 0; nt < 4; ++nt) {
                    uint32_t bf0, bf1;
                    ldm_x2(bf0, bf1, wbase + b_offv[nt] + ks * 32);
                    mma16816(acc[nt], a0, a1, a2, a3, bf0, bf1);
                }
            }
        }
        __syncthreads();
    }

    // ---- epilogue: route to offy/offx/mask ----
    int pbase = b * KT * HW + row * WW;
#pragma unroll
    for (int nt = 0; nt < 4; ++nt) {
        int oc = nt * 8 + (lane & 3) * 2;
#pragma unroll
        for (int half = 0; half < 2; ++half) {
            int px = wid * 16 + (lane >> 2) + half * 8;
#pragma unroll
            for (int e = 0; e < 2; ++e) {
                int o = oc + e;
                if (o >= 27) continue;
                float v = acc[nt][half * 2 + e] + __ldg(&boff[o]);
                if (o < 18) {
                    int q = o >> 1;
                    if ((o & 1) == 0) g_offy[pbase + q * HW + px] = v;
                    else              g_offx[pbase + q * HW + px] = v;
                } else {
                    g_mask[pbase + (o - 18) * HW + px] = 1.0f / (1.0f + __expf(-v));
                }
            }
        }
    }
}

// ---------------- main: gather (NHWC) + mma.sync bf16 hi/lo + bias + relu ----------------
// block = 128 px (one row), 256 threads = 8 warps.
// warp w: px quarter = (w&3)*32 (2 m-tiles of 16), oc half = (w>>2)*32 (4 n-tiles of 8).
#define SM_AHI   0
#define SM_ALO   18432
#define SM_WHI   36864
#define SM_WLO   46080
#define SM_CW    55296
#define SM_CA    73728
#define SM_TOTAL 92160

__global__ void __launch_bounds__(256) dcn_main_kernel(float* __restrict__ out) {
    extern __shared__ char sm[];
    uint32_t smb = smem_u32(sm);
    int tid = threadIdx.x;
    int wid = tid >> 5;
    int lane = tid & 31;

    int b = blockIdx.x >> 7;
    int row = blockIdx.x & 127;

    int pxq = wid & 3;
    int ocg2 = wid >> 2;

    float acc[2][4][4];
#pragma unroll
    for (int mt = 0; mt < 2; ++mt)
#pragma unroll
        for (int nt = 0; nt < 4; ++nt)
#pragma unroll
            for (int i = 0; i < 4; ++i) acc[mt][nt][i] = 0.0f;

    float* cw = (float*)(sm + SM_CW);
    int* ca = (int*)(sm + SM_CA);
    const float4* xq = (const float4*)(g_xT + b * (HW * CIN));

    // ---- precompute coords for ALL 9 taps x 128 px (one barrier) ----
    for (int i = tid; i < KT * 128; i += 256) {
        int k = i >> 7;
        int px = i & 127;
        int off_idx = (b * KT + k) * HW + row * WW + px;
        float oy = g_offy[off_idx];
        float ox = g_offx[off_idx];
        float m  = g_mask[off_idx];
        float py = (float)(row - 1 + k / 3) + oy;
        float pxx = (float)(px - 1 + k % 3) + ox;
        float y0f = floorf(py), x0f = floorf(pxx);
        float ly = py - y0f, lx = pxx - x0f;
        int y0 = (int)y0f, x0 = (int)x0f;
        float vy0 = (y0 >= 0 && y0 < HH) ? 1.0f : 0.0f;
        float vy1 = (y0 + 1 >= 0 && y0 + 1 < HH) ? 1.0f : 0.0f;
        float vx0 = (x0 >= 0 && x0 < WW) ? 1.0f : 0.0f;
        float vx1 = (x0 + 1 >= 0 && x0 + 1 < WW) ? 1.0f : 0.0f;
        float4 wv;
        wv.x = (1.0f - ly) * (1.0f - lx) * m * vy0 * vx0;
        wv.y = (1.0f - ly) * lx * m * vy0 * vx1;
        wv.z = ly * (1.0f - lx) * m * vy1 * vx0;
        wv.w = ly * lx * m * vy1 * vx1;
        int yc0 = min(max(y0, 0), HH - 1);
        int yc1 = min(max(y0 + 1, 0), HH - 1);
        int xc0 = min(max(x0, 0), WW - 1);
        int xc1 = min(max(x0 + 1, 0), WW - 1);
        int4 av;
        av.x = (yc0 * WW + xc0) * 16;
        av.y = (yc0 * WW + xc1) * 16;
        av.z = (yc1 * WW + xc0) * 16;
        av.w = (yc1 * WW + xc1) * 16;
        *(float4*)&cw[i * 4] = wv;
        *(int4*)&ca[i * 4] = av;
    }
    __syncthreads();

    uint32_t a_off[2];
#pragma unroll
    for (int mt = 0; mt < 2; ++mt)
        a_off[mt] = (uint32_t)((pxq * 32 + mt * 16 + (lane & 15)) * (PADC * 2)
                               + (lane >> 4) * 16);
    int l15 = lane & 15;
    uint32_t b_off[4];
#pragma unroll
    for (int nt = 0; nt < 4; ++nt)
        b_off[nt] = (uint32_t)((ocg2 * 32 + nt * 8 + (l15 & 7)) * (PADC * 2)
                               + ((l15 >> 3) & 1) * 16);

#pragma unroll 1
    for (int k = 0; k < KT; ++k) {
        // ---- async W tile copy (overlaps with gather) ----
        {
            const __nv_bfloat16* wh = g_wh + k * 4096;
            const __nv_bfloat16* wl = g_wl + k * 4096;
#pragma unroll
            for (int j = 0; j < 2; ++j) {
                int idx2 = tid + j * 256;      // 0..511
                int o = idx2 >> 3, cc = idx2 & 7;
                cp_async16(smb + SM_WHI + o * (PADC * 2) + cc * 16, wh + o * 64 + cc * 8);
                cp_async16(smb + SM_WLO + o * (PADC * 2) + cc * 16, wl + o * 64 + cc * 8);
            }
        }

        // ---- gather + hi/lo convert + store S tiles [px][ch] ----
        int q = tid & 15;
#pragma unroll 1
        for (int r = 0; r < 8; ++r) {
            int px = r * 16 + (tid >> 4);
            int ci = (k * 128 + px) * 4;
            float4 wv = *(const float4*)&cw[ci];
            int4 av = *(const int4*)&ca[ci];
            float4 v00 = xq[av.x + q];
            float4 v01 = xq[av.y + q];
            float4 v10 = xq[av.z + q];
            float4 v11 = xq[av.w + q];
            float4 v;
            v.x = wv.x * v00.x + wv.y * v01.x + wv.z * v10.x + wv.w * v11.x;
            v.y = wv.x * v00.y + wv.y * v01.y + wv.z * v10.y + wv.w * v11.y;
            v.z = wv.x * v00.z + wv.y * v01.z + wv.z * v10.z + wv.w * v11.z;
            v.w = wv.x * v00.w + wv.y * v01.w + wv.z * v10.w + wv.w * v11.w;

            __nv_bfloat16 hx = __float2bfloat16_rn(v.x);
            __nv_bfloat16 hy = __float2bfloat16_rn(v.y);
            __nv_bfloat16 hz = __float2bfloat16_rn(v.z);
            __nv_bfloat16 hw = __float2bfloat16_rn(v.w);
            __nv_bfloat16 lx2 = __float2bfloat16_rn(v.x - __bfloat162float(hx));
            __nv_bfloat16 ly2 = __float2bfloat16_rn(v.y - __bfloat162float(hy));
            __nv_bfloat16 lz2 = __float2bfloat16_rn(v.z - __bfloat162float(hz));
            __nv_bfloat16 lw2 = __float2bfloat16_rn(v.w - __bfloat162float(hw));
            uint2 hi2, lo2;
            hi2.x = (uint32_t)__bfloat16_as_ushort(hx) | ((uint32_t)__bfloat16_as_ushort(hy) << 16);
            hi2.y = (uint32_t)__bfloat16_as_ushort(hz) | ((uint32_t)__bfloat16_as_ushort(hw) << 16);
            lo2.x = (uint32_t)__bfloat16_as_ushort(lx2) | ((uint32_t)__bfloat16_as_ushort(ly2) << 16);
            lo2.y = (uint32_t)__bfloat16_as_ushort(lz2) | ((uint32_t)__bfloat16_as_ushort(lw2) << 16);

            *(uint2*)(sm + SM_AHI + px * (PADC * 2) + q * 8) = hi2;
            *(uint2*)(sm + SM_ALO + px * (PADC * 2) + q * 8) = lo2;
        }
        cp_async_wait_all();
        __syncthreads();

        // ---- mma: 3 passes (Sh*Wh, Sh*Wl, Sl*Wh) x 4 k16-steps ----
#pragma unroll
        for (int pass = 0; pass < 3; ++pass) {
            uint32_t wbase = smb + ((pass == 1) ? SM_WLO : SM_WHI);
            uint32_t sbase = smb + ((pass == 2) ? SM_ALO : SM_AHI);
#pragma unroll
            for (int ks = 0; ks < 4; ++ks) {
                uint32_t a[2][4];
#pragma unroll
                for (int mt = 0; mt < 2; ++mt)
                    ldm_x4(a[mt][0], a[mt][1], a[mt][2], a[mt][3],
                           sbase + a_off[mt] + ks * 32);
                uint32_t bf[4][2];
#pragma unroll
                for (int nt = 0; nt < 4; ++nt)
                    ldm_x2(bf[nt][0], bf[nt][1], wbase + b_off[nt] + ks * 32);
#pragma unroll
                for (int mt = 0; mt < 2; ++mt)
#pragma unroll
                    for (int nt = 0; nt < 4; ++nt)
                        mma16816(acc[mt][nt], a[mt][0], a[mt][1], a[mt][2], a[mt][3],
                                 bf[nt][0], bf[nt][1]);
            }
        }
        __syncthreads();
    }

    // ---- epilogue: bias + relu ----
    int obase = b * COUT * HW + row * WW;
#pragma unroll
    for (int mt = 0; mt < 2; ++mt) {
        int px = pxq * 32 + mt * 16 + (lane >> 2);
#pragma unroll
        for (int nt = 0; nt < 4; ++nt) {
            int oc = ocg2 * 32 + nt * 8 + (lane & 3) * 2;
            float b0 = __ldg(&g_bias2[oc]);
            float b1 = __ldg(&g_bias2[oc + 1]);
            out[obase + oc * HW + px]           = fmaxf(acc[mt][nt][0] + b0, 0.0f);
            out[obase + (oc + 1) * HW + px]     = fmaxf(acc[mt][nt][1] + b1, 0.0f);
            out[obase + oc * HW + px + 8]       = fmaxf(acc[mt][nt][2] + b0, 0.0f);
            out[obase + (oc + 1) * HW + px + 8] = fmaxf(acc[mt][nt][3] + b1, 0.0f);
        }
    }
}

// ---------------- launch ----------------
extern "C" void kernel_launch(void* const* d_in, const int* in_sizes, int n_in,
                              void* d_out, int out_size) {
    const float* x        = (const float*)d_in[0];
    const float* w_off    = (const float*)d_in[1];
    const float* b_off    = (const float*)d_in[2];
    const float* weight   = (const float*)d_in[3];
    const float* bias     = (const float*)d_in[4];
    const float* gamma    = (const float*)d_in[5];
    const float* beta     = (const float*)d_in[6];
    const float* run_mean = (const float*)d_in[7];
    const float* run_var  = (const float*)d_in[8];
    float* out = (float*)d_out;

    prep_kernel<<<(KT * CIN * COUT + 255) / 256, 256>>>(weight, bias, gamma, beta,
                                                        run_mean, run_var, w_off);

    transpose_kernel<<<BB * 2 * 512, 256>>>(x);

    cudaFuncSetAttribute(offset_mma_kernel,
                         cudaFuncAttributeMaxDynamicSharedMemorySize, OSM_TOTAL);
    offset_mma_kernel<<<BB * HH, 256, OSM_TOTAL>>>(b_off);

    cudaFuncSetAttribute(dcn_main_kernel,
                         cudaFuncAttributeMaxDynamicSharedMemorySize, SM_TOTAL);
    dcn_main_kernel<<<BB * HH, 256, SM_TOTAL>>>(out);
}

// round 9
// speedup vs baseline: 2.2243x; 1.1091x over previous
#include <cuda_runtime.h>
#include <cuda_fp16.h>
#include <math.h>
#include <stdint.h>

#define HH 128
#define WW 128
#define CIN 64
#define COUT 64
#define BB 2
#define KT 9
#define HW (HH*WW)
#define PADB 144   // padded A/W row stride in bytes (72 fp16) — conflict-free ldmatrix

// ---------------- scratch (device globals; no allocation) ----------------
__device__ __align__(16) float g_offy[BB * KT * HW];
__device__ __align__(16) float g_offx[BB * KT * HW];
__device__ __align__(16) float g_mask[BB * KT * HW];
__device__ __align__(16) __half g_xh16[BB * HW * CIN];        // NHWC fp16
__device__ __align__(16) __half g_wh16[KT * COUT * CIN];      // main W [k][o][c] hi (BN folded)
__device__ __align__(16) __half g_wl16[KT * COUT * CIN];      // lo
__device__ __align__(16) __half g_woh16[KT * 32 * CIN];       // offset W [k][oc pad32][c] hi
__device__ __align__(16) __half g_wol16[KT * 32 * CIN];       // lo
__device__ float g_bias2[COUT];

// ---------------- helpers ----------------
__device__ __forceinline__ uint32_t smem_u32(const void* p) {
    uint32_t a;
    asm("{ .reg .u64 t; cvta.to.shared.u64 t, %1; cvt.u32.u64 %0, t; }" : "=r"(a) : "l"(p));
    return a;
}
__device__ __forceinline__ void ldm_x4(uint32_t& r0, uint32_t& r1, uint32_t& r2, uint32_t& r3,
                                       uint32_t addr) {
    asm volatile("ldmatrix.sync.aligned.m8n8.x4.shared.b16 {%0,%1,%2,%3}, [%4];"
        : "=r"(r0), "=r"(r1), "=r"(r2), "=r"(r3) : "r"(addr));
}
__device__ __forceinline__ void ldm_x2(uint32_t& r0, uint32_t& r1, uint32_t addr) {
    asm volatile("ldmatrix.sync.aligned.m8n8.x2.shared.b16 {%0,%1}, [%2];"
        : "=r"(r0), "=r"(r1) : "r"(addr));
}
__device__ __forceinline__ void mma16816(float* d,
                                         uint32_t a0, uint32_t a1, uint32_t a2, uint32_t a3,
                                         uint32_t b0, uint32_t b1) {
    asm volatile(
        "mma.sync.aligned.m16n8k16.row.col.f32.f16.f16.f32 "
        "{%0,%1,%2,%3}, {%4,%5,%6,%7}, {%8,%9}, {%0,%1,%2,%3};"
        : "+f"(d[0]), "+f"(d[1]), "+f"(d[2]), "+f"(d[3])
        : "r"(a0), "r"(a1), "r"(a2), "r"(a3), "r"(b0), "r"(b1));
}
__device__ __forceinline__ void cp_async16(uint32_t dst, const void* src) {
    asm volatile(
        "{ .reg .u64 g; cvta.to.global.u64 g, %1;\n\t"
        "cp.async.ca.shared.global [%0], [g], 16; }"
        :: "r"(dst), "l"(src) : "memory");
}
__device__ __forceinline__ void cp_async_wait_all() {
    asm volatile("cp.async.commit_group;\n\tcp.async.wait_group 0;" ::: "memory");
}
__device__ __forceinline__ void bar_sync(int id, int cnt) {
    asm volatile("bar.sync %0, %1;" :: "r"(id), "r"(cnt) : "memory");
}
__device__ __forceinline__ void bar_arrive(int id, int cnt) {
    asm volatile("bar.arrive %0, %1;" :: "r"(id), "r"(cnt) : "memory");
}

// ---------------- prep: fold BN; fp16 hi/lo weight tiles ----------------
__global__ void prep_kernel(const float* __restrict__ weight,
                            const float* __restrict__ bias,
                            const float* __restrict__ gamma,
                            const float* __restrict__ beta,
                            const float* __restrict__ run_mean,
                            const float* __restrict__ run_var,
                            const float* __restrict__ w_off) {
    int idx = blockIdx.x * blockDim.x + threadIdx.x;
    if (idx < COUT) {
        float inv = gamma[idx] * rsqrtf(run_var[idx] + 1e-5f);
        g_bias2[idx] = (bias[idx] - run_mean[idx]) * inv + beta[idx];
    }
    if (idx < KT * CIN * COUT) {
        int k = idx >> 12;
        int c = (idx >> 6) & 63;
        int o = idx & 63;
        float inv = gamma[o] * rsqrtf(run_var[o] + 1e-5f);
        float val = weight[(o * CIN + c) * KT + k] * inv;
        __half hi = __float2half_rn(val);
        __half lo = __float2half_rn(val - __half2float(hi));
        g_wh16[k * 4096 + o * 64 + c] = hi;
        g_wl16[k * 4096 + o * 64 + c] = lo;
    }
    if (idx < KT * 32 * CIN) {
        int k = idx >> 11;
        int o = (idx >> 6) & 31;
        int c = idx & 63;
        float val = (o < 27) ? w_off[(o * CIN + c) * KT + k] : 0.0f;
        __half hi = __float2half_rn(val);
        __half lo = __float2half_rn(val - __half2float(hi));
        g_woh16[idx] = hi;
        g_wol16[idx] = lo;
    }
}

// ---------------- transpose x: NCHW fp32 -> NHWC fp16 ----------------
__global__ void transpose_kernel(const float* __restrict__ x) {
    __shared__ float t[32][33];
    int bid = blockIdx.x;
    int ct = bid & 1;
    int pt = (bid >> 1) & 511;
    int b = bid >> 10;
    int c0 = ct * 32, p0 = pt * 32;
    int tid = threadIdx.x;

#pragma unroll
    for (int pass = 0; pass < 4; ++pass) {
        int cl = (tid >> 5) + pass * 8;
        t[cl][tid & 31] = x[(b * CIN + c0 + cl) * HW + p0 + (tid & 31)];
    }
    __syncthreads();
    int p = tid >> 3, cc = tid & 7;
    float4 v = make_float4(t[cc * 4 + 0][p], t[cc * 4 + 1][p],
                           t[cc * 4 + 2][p], t[cc * 4 + 3][p]);
    int base = (b * HW + p0 + p) * CIN + c0 + cc * 4;
    __half2 h01 = __floats2half2_rn(v.x, v.y);
    __half2 h23 = __floats2half2_rn(v.z, v.w);
    uint2 hv;
    hv.x = *(uint32_t*)&h01;
    hv.y = *(uint32_t*)&h23;
    *(uint2*)&g_xh16[base] = hv;
}

// ---------------- offset conv as mma GEMM (fp16, 2-pass) ----------------
// block = one row (128 px), 256 threads = 8 warps (each warp: 16 px x 32 oc).
#define OSM_A     0
#define OSM_WH    18432
#define OSM_WL    23040
#define OSM_TOTAL 27648

__global__ void __launch_bounds__(256) offset_mma_kernel(const float* __restrict__ boff) {
    extern __shared__ char sm[];
    uint32_t smb = smem_u32(sm);
    int tid = threadIdx.x;
    int wid = tid >> 5;
    int lane = tid & 31;

    int b = blockIdx.x >> 7;
    int row = blockIdx.x & 127;

    float acc[4][4];
#pragma unroll
    for (int nt = 0; nt < 4; ++nt)
#pragma unroll
        for (int i = 0; i < 4; ++i) acc[nt][i] = 0.0f;

    uint32_t a_off = (uint32_t)((wid * 16 + (lane & 15)) * PADB + (lane >> 4) * 16);
    int l15 = lane & 15;
    uint32_t b_offv[4];
#pragma unroll
    for (int nt = 0; nt < 4; ++nt)
        b_offv[nt] = (uint32_t)((nt * 8 + (l15 & 7)) * PADB + ((l15 >> 3) & 1) * 16);

#pragma unroll 1
    for (int k = 0; k < KT; ++k) {
        int ty = k / 3, tx = k % 3;
        int rr = row - 1 + ty;
        bool row_ok = (rr >= 0) && (rr < HH);

        // W tile: 32 oc x 128B, hi+lo (256 chunks each)
        {
            int o = tid >> 3, cc = tid & 7;
            cp_async16(smb + OSM_WH + o * PADB + cc * 16, g_woh16 + k * 2048 + o * 64 + cc * 8);
            cp_async16(smb + OSM_WL + o * PADB + cc * 16, g_wol16 + k * 2048 + o * 64 + cc * 8);
        }
        // A tile: 128 px rows of 128B fp16, shifted by (rr, tx-1)
#pragma unroll
        for (int j = 0; j < 4; ++j) {
            int idx2 = tid + j * 256;          // 0..1023
            int px = idx2 >> 3, cc = idx2 & 7;
            int sc = px - 1 + tx;
            bool ok = row_ok && (sc >= 0) && (sc < WW);
            if (ok) {
                cp_async16(smb + OSM_A + px * PADB + cc * 16,
                           g_xh16 + (b * HW + rr * WW + sc) * 64 + cc * 8);
            } else {
                uint4 z = make_uint4(0, 0, 0, 0);
                *(uint4*)(sm + OSM_A + px * PADB + cc * 16) = z;
            }
        }
        cp_async_wait_all();
        __syncthreads();

        // mma: 2 passes (A*Wh, A*Wl) x 4 k16-steps
#pragma unroll
        for (int ks = 0; ks < 4; ++ks) {
            uint32_t a0, a1, a2, a3;
            ldm_x4(a0, a1, a2, a3, smb + OSM_A + a_off + ks * 32);
#pragma unroll
            for (int pass = 0; pass < 2; ++pass) {
                uint32_t wb = smb + ((pass == 0) ? OSM_WH : OSM_WL);
#pragma unroll
                for (int nt = 0; nt < 4; ++nt) {
                    uint32_t bf0, bf1;
                    ldm_x2(bf0, bf1, wb + b_offv[nt] + ks * 32);
                    mma16816(acc[nt], a0, a1, a2, a3, bf0, bf1);
                }
            }
        }
        __syncthreads();
    }

    // ---- epilogue: route to offy/offx/mask ----
    int pbase = b * KT * HW + row * WW;
#pragma unroll
    for (int nt = 0; nt < 4; ++nt) {
        int oc = nt * 8 + (lane & 3) * 2;
#pragma unroll
        for (int half = 0; half < 2; ++half) {
            int px = wid * 16 + (lane >> 2) + half * 8;
#pragma unroll
            for (int e = 0; e < 2; ++e) {
                int o = oc + e;
                if (o >= 27) continue;
                float v = acc[nt][half * 2 + e] + __ldg(&boff[o]);
                if (o < 18) {
                    int q = o >> 1;
                    if ((o & 1) == 0) g_offy[pbase + q * HW + px] = v;
                    else              g_offx[pbase + q * HW + px] = v;
                } else {
                    g_mask[pbase + (o - 18) * HW + px] = 1.0f / (1.0f + __expf(-v));
                }
            }
        }
    }
}

// ---------------- main: warp-specialized gather + mma (fp16, 2-pass) ----------------
// 256 threads: warps 0-3 = consumers (MMA, 32px x 64oc each), warps 4-7 = producers.
// Double-buffered A (fp16 S tile) and W (hi+lo) smem; named-barrier full/empty pairs.
#define SM_A0    0
#define SM_A1    18432
#define SM_W0    36864        // Wh at +0, Wl at +9216
#define SM_W1    55296
#define SM_CW    73728
#define SM_CA    92160
#define SM_TOTAL 110592

__global__ void __launch_bounds__(256, 2) dcn_main_kernel(float* __restrict__ out) {
    extern __shared__ char sm[];
    uint32_t smb = smem_u32(sm);
    int tid = threadIdx.x;
    int wid = tid >> 5;
    int lane = tid & 31;

    int b = blockIdx.x >> 7;
    int row = blockIdx.x & 127;

    if (wid >= 4) {
        // ================= producers =================
        int ptid = tid & 127;
        float* cw = (float*)(sm + SM_CW);
        int* ca = (int*)(sm + SM_CA);
        const uint2* xh = (const uint2*)(g_xh16 + b * (HW * CIN));

        // coords for all 9 taps x 128 px
        for (int i = ptid; i < KT * 128; i += 128) {
            int k = i >> 7;
            int px = i & 127;
            int off_idx = (b * KT + k) * HW + row * WW + px;
            float oy = g_offy[off_idx];
            float ox = g_offx[off_idx];
            float m  = g_mask[off_idx];
            float py = (float)(row - 1 + k / 3) + oy;
            float pxx = (float)(px - 1 + k % 3) + ox;
            float y0f = floorf(py), x0f = floorf(pxx);
            float ly = py - y0f, lx = pxx - x0f;
            int y0 = (int)y0f, x0 = (int)x0f;
            float vy0 = (y0 >= 0 && y0 < HH) ? 1.0f : 0.0f;
            float vy1 = (y0 + 1 >= 0 && y0 + 1 < HH) ? 1.0f : 0.0f;
            float vx0 = (x0 >= 0 && x0 < WW) ? 1.0f : 0.0f;
            float vx1 = (x0 + 1 >= 0 && x0 + 1 < WW) ? 1.0f : 0.0f;
            float4 wv;
            wv.x = (1.0f - ly) * (1.0f - lx) * m * vy0 * vx0;
            wv.y = (1.0f - ly) * lx * m * vy0 * vx1;
            wv.z = ly * (1.0f - lx) * m * vy1 * vx0;
            wv.w = ly * lx * m * vy1 * vx1;
            int yc0 = min(max(y0, 0), HH - 1);
            int yc1 = min(max(y0 + 1, 0), HH - 1);
            int xc0 = min(max(x0, 0), WW - 1);
            int xc1 = min(max(x0 + 1, 0), WW - 1);
            int4 av;
            av.x = (yc0 * WW + xc0) * 16;   // uint2 index (8B units): pos*128B/8
            av.y = (yc0 * WW + xc1) * 16;
            av.z = (yc1 * WW + xc0) * 16;
            av.w = (yc1 * WW + xc1) * 16;
            *(float4*)&cw[i * 4] = wv;
            *(int4*)&ca[i * 4] = av;
        }
        bar_sync(5, 128);   // producers only

        int q = ptid & 15;
        int sub = ptid >> 4;

#pragma unroll 1
        for (int k = 0; k < KT; ++k) {
            int p = k & 1;
            if (k >= 2) bar_sync(3 + p, 256);   // wait buffer empty

            // W tiles hi+lo via cp.async (512 chunks each, 4 per thread)
            uint32_t wdst = smb + (p ? SM_W1 : SM_W0);
            const __half* wh = g_wh16 + k * 4096;
            const __half* wl = g_wl16 + k * 4096;
#pragma unroll
            for (int j = 0; j < 4; ++j) {
                int idx2 = ptid + j * 128;
                int o = idx2 >> 3, cc = idx2 & 7;
                cp_async16(wdst + o * PADB + cc * 16, wh + o * 64 + cc * 8);
                cp_async16(wdst + 9216 + o * PADB + cc * 16, wl + o * 64 + cc * 8);
            }

            // gather from fp16 NHWC image
            char* adst = sm + (p ? SM_A1 : SM_A0);
#pragma unroll 1
            for (int r = 0; r < 16; ++r) {
                int px = r * 8 + sub;
                int ci = (k * 128 + px) * 4;
                float4 wv = *(const float4*)&cw[ci];
                int4 av = *(const int4*)&ca[ci];
                uint2 r00 = xh[av.x + q];
                uint2 r01 = xh[av.y + q];
                uint2 r10 = xh[av.z + q];
                uint2 r11 = xh[av.w + q];
                float2 c00a = __half22float2(*(const __half2*)&r00.x);
                float2 c00b = __half22float2(*(const __half2*)&r00.y);
                float2 c01a = __half22float2(*(const __half2*)&r01.x);
                float2 c01b = __half22float2(*(const __half2*)&r01.y);
                float2 c10a = __half22float2(*(const __half2*)&r10.x);
                float2 c10b = __half22float2(*(const __half2*)&r10.y);
                float2 c11a = __half22float2(*(const __half2*)&r11.x);
                float2 c11b = __half22float2(*(const __half2*)&r11.y);
                float v0 = wv.x * c00a.x + wv.y * c01a.x + wv.z * c10a.x + wv.w * c11a.x;
                float v1 = wv.x * c00a.y + wv.y * c01a.y + wv.z * c10a.y + wv.w * c11a.y;
                float v2 = wv.x * c00b.x + wv.y * c01b.x + wv.z * c10b.x + wv.w * c11b.x;
                float v3 = wv.x * c00b.y + wv.y * c01b.y + wv.z * c10b.y + wv.w * c11b.y;
                __half2 h01 = __floats2half2_rn(v0, v1);
                __half2 h23 = __floats2half2_rn(v2, v3);
                uint2 hv;
                hv.x = *(uint32_t*)&h01;
                hv.y = *(uint32_t*)&h23;
                *(uint2*)(adst + px * PADB + q * 8) = hv;
            }
            cp_async_wait_all();
            bar_arrive(1 + p, 256);             // buffer full
        }
    } else {
        // ================= consumers =================
        int px0 = wid * 32;

        float acc[2][8][4];
#pragma unroll
        for (int mt = 0; mt < 2; ++mt)
#pragma unroll
            for (int nt = 0; nt < 8; ++nt)
#pragma unroll
                for (int i = 0; i < 4; ++i) acc[mt][nt][i] = 0.0f;

        uint32_t a_off[2];
#pragma unroll
        for (int mt = 0; mt < 2; ++mt)
            a_off[mt] = (uint32_t)((px0 + mt * 16 + (lane & 15)) * PADB + (lane >> 4) * 16);
        int l15 = lane & 15;
        uint32_t b_off[8];
#pragma unroll
        for (int nt = 0; nt < 8; ++nt)
            b_off[nt] = (uint32_t)((nt * 8 + (l15 & 7)) * PADB + ((l15 >> 3) & 1) * 16);

#pragma unroll 1
        for (int k = 0; k < KT; ++k) {
            int p = k & 1;
            bar_sync(1 + p, 256);               // wait buffer full
            uint32_t ab = smb + (p ? SM_A1 : SM_A0);
            uint32_t wbb = smb + (p ? SM_W1 : SM_W0);
#pragma unroll
            for (int ks = 0; ks < 4; ++ks) {
                uint32_t a[2][4];
#pragma unroll
                for (int mt = 0; mt < 2; ++mt)
                    ldm_x4(a[mt][0], a[mt][1], a[mt][2], a[mt][3],
                           ab + a_off[mt] + ks * 32);
#pragma unroll
                for (int pass = 0; pass < 2; ++pass) {
                    uint32_t wb = wbb + pass * 9216;
#pragma unroll
                    for (int nt = 0; nt < 8; ++nt) {
                        uint32_t bf0, bf1;
                        ldm_x2(bf0, bf1, wb + b_off[nt] + ks * 32);
                        mma16816(acc[0][nt], a[0][0], a[0][1], a[0][2], a[0][3], bf0, bf1);
                        mma16816(acc[1][nt], a[1][0], a[1][1], a[1][2], a[1][3], bf0, bf1);
                    }
                }
            }
            bar_arrive(3 + p, 256);             // buffer empty
        }

        // ---- epilogue: bias + relu ----
        int obase = b * COUT * HW + row * WW;
#pragma unroll
        for (int mt = 0; mt < 2; ++mt) {
            int px = px0 + mt * 16 + (lane >> 2);
#pragma unroll
            for (int nt = 0; nt < 8; ++nt) {
                int oc = nt * 8 + (lane & 3) * 2;
                float b0 = __ldg(&g_bias2[oc]);
                float b1 = __ldg(&g_bias2[oc + 1]);
                out[obase + oc * HW + px]           = fmaxf(acc[mt][nt][0] + b0, 0.0f);
                out[obase + (oc + 1) * HW + px]     = fmaxf(acc[mt][nt][1] + b1, 0.0f);
                out[obase + oc * HW + px + 8]       = fmaxf(acc[mt][nt][2] + b0, 0.0f);
                out[obase + (oc + 1) * HW + px + 8] = fmaxf(acc[mt][nt][3] + b1, 0.0f);
            }
        }
    }
}

// ---------------- launch ----------------
extern "C" void kernel_launch(void* const* d_in, const int* in_sizes, int n_in,
                              void* d_out, int out_size) {
    const float* x        = (const float*)d_in[0];
    const float* w_off    = (const float*)d_in[1];
    const float* b_off    = (const float*)d_in[2];
    const float* weight   = (const float*)d_in[3];
    const float* bias     = (const float*)d_in[4];
    const float* gamma    = (const float*)d_in[5];
    const float* beta     = (const float*)d_in[6];
    const float* run_mean = (const float*)d_in[7];
    const float* run_var  = (const float*)d_in[8];
    float* out = (float*)d_out;

    prep_kernel<<<(KT * CIN * COUT + 255) / 256, 256>>>(weight, bias, gamma, beta,
                                                        run_mean, run_var, w_off);

    transpose_kernel<<<BB * 2 * 512, 256>>>(x);

    cudaFuncSetAttribute(offset_mma_kernel,
                         cudaFuncAttributeMaxDynamicSharedMemorySize, OSM_TOTAL);
    offset_mma_kernel<<<BB * HH, 256, OSM_TOTAL>>>(b_off);

    cudaFuncSetAttribute(dcn_main_kernel,
                         cudaFuncAttributeMaxDynamicSharedMemorySize, SM_TOTAL);
    dcn_main_kernel<<<BB * HH, 256, SM_TOTAL>>>(out);
}

// round 11
// speedup vs baseline: 2.8162x; 1.2662x over previous
#include <cuda_runtime.h>
#include <cuda_fp16.h>
#include <math.h>
#include <stdint.h>

#define HH 128
#define WW 128
#define CIN 64
#define COUT 64
#define BB 2
#define KT 9
#define HW (HH*WW)
#define PADB 144   // padded A/W row stride in bytes (72 fp16) — conflict-free ldmatrix

// ---------------- scratch (device globals; no allocation) ----------------
__device__ __align__(16) float g_offy[BB * KT * HW];
__device__ __align__(16) float g_offx[BB * KT * HW];
__device__ __align__(16) float g_mask[BB * KT * HW];
__device__ __align__(16) __half g_xh16[BB * HW * CIN];        // NHWC fp16
__device__ __align__(16) __half g_wh16[KT * COUT * CIN];      // main W [k][o][c] hi (BN folded)
__device__ __align__(16) __half g_wl16[KT * COUT * CIN];      // lo
__device__ __align__(16) __half g_woh16[KT * 32 * CIN];       // offset W [k][oc pad32][c] hi
__device__ __align__(16) __half g_wol16[KT * 32 * CIN];       // lo
__device__ float g_bias2[COUT];

// ---------------- helpers ----------------
__device__ __forceinline__ uint32_t smem_u32(const void* p) {
    uint32_t a;
    asm("{ .reg .u64 t; cvta.to.shared.u64 t, %1; cvt.u32.u64 %0, t; }" : "=r"(a) : "l"(p));
    return a;
}
__device__ __forceinline__ void ldm_x4(uint32_t& r0, uint32_t& r1, uint32_t& r2, uint32_t& r3,
                                       uint32_t addr) {
    asm volatile("ldmatrix.sync.aligned.m8n8.x4.shared.b16 {%0,%1,%2,%3}, [%4];"
        : "=r"(r0), "=r"(r1), "=r"(r2), "=r"(r3) : "r"(addr));
}
__device__ __forceinline__ void ldm_x2(uint32_t& r0, uint32_t& r1, uint32_t addr) {
    asm volatile("ldmatrix.sync.aligned.m8n8.x2.shared.b16 {%0,%1}, [%2];"
        : "=r"(r0), "=r"(r1) : "r"(addr));
}
__device__ __forceinline__ void mma16816(float* d,
                                         uint32_t a0, uint32_t a1, uint32_t a2, uint32_t a3,
                                         uint32_t b0, uint32_t b1) {
    asm volatile(
        "mma.sync.aligned.m16n8k16.row.col.f32.f16.f16.f32 "
        "{%0,%1,%2,%3}, {%4,%5,%6,%7}, {%8,%9}, {%0,%1,%2,%3};"
        : "+f"(d[0]), "+f"(d[1]), "+f"(d[2]), "+f"(d[3])
        : "r"(a0), "r"(a1), "r"(a2), "r"(a3), "r"(b0), "r"(b1));
}
__device__ __forceinline__ void cp_async16(uint32_t dst, const void* src) {
    asm volatile(
        "{ .reg .u64 g; cvta.to.global.u64 g, %1;\n\t"
        "cp.async.ca.shared.global [%0], [g], 16; }"
        :: "r"(dst), "l"(src) : "memory");
}
__device__ __forceinline__ void cp_async_wait_all() {
    asm volatile("cp.async.commit_group;\n\tcp.async.wait_group 0;" ::: "memory");
}

// ---------------- prep: fold BN; fp16 hi/lo weight tiles ----------------
__global__ void prep_kernel(const float* __restrict__ weight,
                            const float* __restrict__ bias,
                            const float* __restrict__ gamma,
                            const float* __restrict__ beta,
                            const float* __restrict__ run_mean,
                            const float* __restrict__ run_var,
                            const float* __restrict__ w_off) {
    int idx = blockIdx.x * blockDim.x + threadIdx.x;
    if (idx < COUT) {
        float inv = gamma[idx] * rsqrtf(run_var[idx] + 1e-5f);
        g_bias2[idx] = (bias[idx] - run_mean[idx]) * inv + beta[idx];
    }
    if (idx < KT * CIN * COUT) {
        int k = idx >> 12;
        int c = (idx >> 6) & 63;
        int o = idx & 63;
        float inv = gamma[o] * rsqrtf(run_var[o] + 1e-5f);
        float val = weight[(o * CIN + c) * KT + k] * inv;
        __half hi = __float2half_rn(val);
        __half lo = __float2half_rn(val - __half2float(hi));
        g_wh16[k * 4096 + o * 64 + c] = hi;
        g_wl16[k * 4096 + o * 64 + c] = lo;
    }
    if (idx < KT * 32 * CIN) {
        int k = idx >> 11;
        int o = (idx >> 6) & 31;
        int c = idx & 63;
        float val = (o < 27) ? w_off[(o * CIN + c) * KT + k] : 0.0f;
        __half hi = __float2half_rn(val);
        __half lo = __float2half_rn(val - __half2float(hi));
        g_woh16[idx] = hi;
        g_wol16[idx] = lo;
    }
}

// ---------------- transpose x: NCHW fp32 -> NHWC fp16 ----------------
__global__ void transpose_kernel(const float* __restrict__ x) {
    __shared__ float t[32][33];
    int bid = blockIdx.x;
    int ct = bid & 1;
    int pt = (bid >> 1) & 511;
    int b = bid >> 10;
    int c0 = ct * 32, p0 = pt * 32;
    int tid = threadIdx.x;

#pragma unroll
    for (int pass = 0; pass < 4; ++pass) {
        int cl = (tid >> 5) + pass * 8;
        t[cl][tid & 31] = x[(b * CIN + c0 + cl) * HW + p0 + (tid & 31)];
    }
    __syncthreads();
    int p = tid >> 3, cc = tid & 7;
    float4 v = make_float4(t[cc * 4 + 0][p], t[cc * 4 + 1][p],
                           t[cc * 4 + 2][p], t[cc * 4 + 3][p]);
    int base = (b * HW + p0 + p) * CIN + c0 + cc * 4;
    __half2 h01 = __floats2half2_rn(v.x, v.y);
    __half2 h23 = __floats2half2_rn(v.z, v.w);
    uint2 hv;
    hv.x = *(uint32_t*)&h01;
    hv.y = *(uint32_t*)&h23;
    *(uint2*)&g_xh16[base] = hv;
}

// ---------------- offset conv as mma GEMM (fp16, 2-pass) ----------------
#define OSM_A     0
#define OSM_WH    18432
#define OSM_WL    23040
#define OSM_TOTAL 27648

__global__ void __launch_bounds__(256) offset_mma_kernel(const float* __restrict__ boff) {
    extern __shared__ char sm[];
    uint32_t smb = smem_u32(sm);
    int tid = threadIdx.x;
    int wid = tid >> 5;
    int lane = tid & 31;

    int b = blockIdx.x >> 7;
    int row = blockIdx.x & 127;

    float acc[4][4];
#pragma unroll
    for (int nt = 0; nt < 4; ++nt)
#pragma unroll
        for (int i = 0; i < 4; ++i) acc[nt][i] = 0.0f;

    uint32_t a_off = (uint32_t)((wid * 16 + (lane & 15)) * PADB + (lane >> 4) * 16);
    int l15 = lane & 15;
    uint32_t b_offv[4];
#pragma unroll
    for (int nt = 0; nt < 4; ++nt)
        b_offv[nt] = (uint32_t)((nt * 8 + (l15 & 7)) * PADB + ((l15 >> 3) & 1) * 16);

#pragma unroll 1
    for (int k = 0; k < KT; ++k) {
        int ty = k / 3, tx = k % 3;
        int rr = row - 1 + ty;
        bool row_ok = (rr >= 0) && (rr < HH);

        {
            int o = tid >> 3, cc = tid & 7;
            cp_async16(smb + OSM_WH + o * PADB + cc * 16, g_woh16 + k * 2048 + o * 64 + cc * 8);
            cp_async16(smb + OSM_WL + o * PADB + cc * 16, g_wol16 + k * 2048 + o * 64 + cc * 8);
        }
#pragma unroll
        for (int j = 0; j < 4; ++j) {
            int idx2 = tid + j * 256;
            int px = idx2 >> 3, cc = idx2 & 7;
            int sc = px - 1 + tx;
            bool ok = row_ok && (sc >= 0) && (sc < WW);
            if (ok) {
                cp_async16(smb + OSM_A + px * PADB + cc * 16,
                           g_xh16 + (b * HW + rr * WW + sc) * 64 + cc * 8);
            } else {
                uint4 z = make_uint4(0, 0, 0, 0);
                *(uint4*)(sm + OSM_A + px * PADB + cc * 16) = z;
            }
        }
        cp_async_wait_all();
        __syncthreads();

#pragma unroll
        for (int ks = 0; ks < 4; ++ks) {
            uint32_t a0, a1, a2, a3;
            ldm_x4(a0, a1, a2, a3, smb + OSM_A + a_off + ks * 32);
#pragma unroll
            for (int pass = 0; pass < 2; ++pass) {
                uint32_t wb = smb + ((pass == 0) ? OSM_WH : OSM_WL);
#pragma unroll
                for (int nt = 0; nt < 4; ++nt) {
                    uint32_t bf0, bf1;
                    ldm_x2(bf0, bf1, wb + b_offv[nt] + ks * 32);
                    mma16816(acc[nt], a0, a1, a2, a3, bf0, bf1);
                }
            }
        }
        __syncthreads();
    }

    int pbase = b * KT * HW + row * WW;
#pragma unroll
    for (int nt = 0; nt < 4; ++nt) {
        int oc = nt * 8 + (lane & 3) * 2;
#pragma unroll
        for (int half = 0; half < 2; ++half) {
            int px = wid * 16 + (lane >> 2) + half * 8;
#pragma unroll
            for (int e = 0; e < 2; ++e) {
                int o = oc + e;
                if (o >= 27) continue;
                float v = acc[nt][half * 2 + e] + __ldg(&boff[o]);
                if (o < 18) {
                    int q = o >> 1;
                    if ((o & 1) == 0) g_offy[pbase + q * HW + px] = v;
                    else              g_offx[pbase + q * HW + px] = v;
                } else {
                    g_mask[pbase + (o - 18) * HW + px] = 1.0f / (1.0f + __expf(-v));
                }
            }
        }
    }
}

// ---------------- main: homogeneous 8-warp, double-buffered, fp16 2-pass ----------------
// 256 threads; warp w: px quarter (w&3)*32 (2 m-tiles), oc half (w>>2)*32 (4 n-tiles).
// Per tap: issue half gather LDGs -> mma 2 k-steps -> convert/store -> second half -> 1 barrier.
#define SM_A0    0
#define SM_A1    18432
#define SM_W0    36864        // hi at +0, lo at +9216
#define SM_W1    55296
#define SM_CW    73728
#define SM_CA    92160
#define SM_TOTAL 110592

__device__ __forceinline__ void issue_w(uint32_t wdst, const __half* wh, const __half* wl,
                                        int tid) {
#pragma unroll
    for (int j = 0; j < 2; ++j) {
        int idx2 = tid + j * 256;
        int o = idx2 >> 3, cc = idx2 & 7;
        cp_async16(wdst + o * PADB + cc * 16, wh + o * 64 + cc * 8);
        cp_async16(wdst + 9216 + o * PADB + cc * 16, wl + o * 64 + cc * 8);
    }
}

__device__ __forceinline__ void gather_load(const uint2* __restrict__ xh,
                                            const int4* __restrict__ ca,
                                            int k, int r0, int q, int sub, uint2* L) {
#pragma unroll
    for (int rr = 0; rr < 4; ++rr) {
        int px = (r0 + rr) * 16 + sub;
        int4 av = ca[k * 128 + px];
        L[rr * 4 + 0] = xh[av.x + q];
        L[rr * 4 + 1] = xh[av.y + q];
        L[rr * 4 + 2] = xh[av.z + q];
        L[rr * 4 + 3] = xh[av.w + q];
    }
}

__device__ __forceinline__ void gather_store(const float4* __restrict__ cwf,
                                             int k, int r0, int q, int sub,
                                             const uint2* L, char* adst) {
#pragma unroll
    for (int rr = 0; rr < 4; ++rr) {
        int px = (r0 + rr) * 16 + sub;
        float4 wv = cwf[k * 128 + px];
        uint2 r00 = L[rr * 4 + 0];
        uint2 r01 = L[rr * 4 + 1];
        uint2 r10 = L[rr * 4 + 2];
        uint2 r11 = L[rr * 4 + 3];
        float2 c00a = __half22float2(*(const __half2*)&r00.x);
        float2 c00b = __half22float2(*(const __half2*)&r00.y);
        float2 c01a = __half22float2(*(const __half2*)&r01.x);
        float2 c01b = __half22float2(*(const __half2*)&r01.y);
        float2 c10a = __half22float2(*(const __half2*)&r10.x);
        float2 c10b = __half22float2(*(const __half2*)&r10.y);
        float2 c11a = __half22float2(*(const __half2*)&r11.x);
        float2 c11b = __half22float2(*(const __half2*)&r11.y);
        float v0 = wv.x * c00a.x + wv.y * c01a.x + wv.z * c10a.x + wv.w * c11a.x;
        float v1 = wv.x * c00a.y + wv.y * c01a.y + wv.z * c10a.y + wv.w * c11a.y;
        float v2 = wv.x * c00b.x + wv.y * c01b.x + wv.z * c10b.x + wv.w * c11b.x;
        float v3 = wv.x * c00b.y + wv.y * c01b.y + wv.z * c10b.y + wv.w * c11b.y;
        __half2 h01 = __floats2half2_rn(v0, v1);
        __half2 h23 = __floats2half2_rn(v2, v3);
        uint2 hv;
        hv.x = *(uint32_t*)&h01;
        hv.y = *(uint32_t*)&h23;
        *(uint2*)(adst + px * PADB + q * 8) = hv;
    }
}

__device__ __forceinline__ void mma_two_ks(uint32_t ab, uint32_t wbb, int ks0,
                                           const uint32_t* a_off, const uint32_t* b_off,
                                           float acc[2][4][4]) {
#pragma unroll
    for (int ks = ks0; ks < ks0 + 2; ++ks) {
        uint32_t a[2][4];
#pragma unroll
        for (int mt = 0; mt < 2; ++mt)
            ldm_x4(a[mt][0], a[mt][1], a[mt][2], a[mt][3], ab + a_off[mt] + ks * 32);
#pragma unroll
        for (int pass = 0; pass < 2; ++pass) {
            uint32_t wb = wbb + pass * 9216;
#pragma unroll
            for (int nt = 0; nt < 4; ++nt) {
                uint32_t bf0, bf1;
                ldm_x2(bf0, bf1, wb + b_off[nt] + ks * 32);
                mma16816(acc[0][nt], a[0][0], a[0][1], a[0][2], a[0][3], bf0, bf1);
                mma16816(acc[1][nt], a[1][0], a[1][1], a[1][2], a[1][3], bf0, bf1);
            }
        }
    }
}

__global__ void __launch_bounds__(256, 2) dcn_main_kernel(float* __restrict__ out) {
    extern __shared__ char sm[];
    uint32_t smb = smem_u32(sm);
    int tid = threadIdx.x;
    int wid = tid >> 5;
    int lane = tid & 31;

    int b = blockIdx.x >> 7;
    int row = blockIdx.x & 127;

    int pxq = wid & 3;
    int ocg2 = wid >> 2;
    int q = tid & 15;
    int sub = tid >> 4;

    float acc[2][4][4];
#pragma unroll
    for (int mt = 0; mt < 2; ++mt)
#pragma unroll
        for (int nt = 0; nt < 4; ++nt)
#pragma unroll
            for (int i = 0; i < 4; ++i) acc[mt][nt][i] = 0.0f;

    float4* cwf = (float4*)(sm + SM_CW);
    int4* ca = (int4*)(sm + SM_CA);
    const uint2* xh = (const uint2*)(g_xh16 + b * (HW * CIN));

    // ---- coords for all 9 taps x 128 px ----
    for (int i = tid; i < KT * 128; i += 256) {
        int k = i >> 7;
        int px = i & 127;
        int off_idx = (b * KT + k) * HW + row * WW + px;
        float oy = g_offy[off_idx];
        float ox = g_offx[off_idx];
        float m  = g_mask[off_idx];
        float py = (float)(row - 1 + k / 3) + oy;
        float pxx = (float)(px - 1 + k % 3) + ox;
        float y0f = floorf(py), x0f = floorf(pxx);
        float ly = py - y0f, lx = pxx - x0f;
        int y0 = (int)y0f, x0 = (int)x0f;
        float vy0 = (y0 >= 0 && y0 < HH) ? 1.0f : 0.0f;
        float vy1 = (y0 + 1 >= 0 && y0 + 1 < HH) ? 1.0f : 0.0f;
        float vx0 = (x0 >= 0 && x0 < WW) ? 1.0f : 0.0f;
        float vx1 = (x0 + 1 >= 0 && x0 + 1 < WW) ? 1.0f : 0.0f;
        float4 wv;
        wv.x = (1.0f - ly) * (1.0f - lx) * m * vy0 * vx0;
        wv.y = (1.0f - ly) * lx * m * vy0 * vx1;
        wv.z = ly * (1.0f - lx) * m * vy1 * vx0;
        wv.w = ly * lx * m * vy1 * vx1;
        int yc0 = min(max(y0, 0), HH - 1);
        int yc1 = min(max(y0 + 1, 0), HH - 1);
        int xc0 = min(max(x0, 0), WW - 1);
        int xc1 = min(max(x0 + 1, 0), WW - 1);
        int4 av;
        av.x = (yc0 * WW + xc0) * 16;   // uint2 index: pos*128B/8B
        av.y = (yc0 * WW + xc1) * 16;
        av.z = (yc1 * WW + xc0) * 16;
        av.w = (yc1 * WW + xc1) * 16;
        cwf[i] = wv;
        ca[i] = av;
    }
    __syncthreads();

    uint32_t a_off[2];
#pragma unroll
    for (int mt = 0; mt < 2; ++mt)
        a_off[mt] = (uint32_t)((pxq * 32 + mt * 16 + (lane & 15)) * PADB + (lane >> 4) * 16);
    int l15 = lane & 31 & 15;
    uint32_t b_off[4];
#pragma unroll
    for (int nt = 0; nt < 4; ++nt)
        b_off[nt] = (uint32_t)((ocg2 * 32 + nt * 8 + (l15 & 7)) * PADB + ((l15 >> 3) & 1) * 16);

    // ---- prologue: fill buffer 0 with tap 0 ----
    issue_w(smb + SM_W0, g_wh16, g_wl16, tid);
    {
        uint2 L[16];
        gather_load(xh, ca, 0, 0, q, sub, L);
        gather_store(cwf, 0, 0, q, sub, L, sm + SM_A0);
        gather_load(xh, ca, 0, 4, q, sub, L);
        gather_store(cwf, 0, 4, q, sub, L, sm + SM_A0);
    }
    cp_async_wait_all();
    __syncthreads();

    // ---- pipelined main loop: 1 barrier per tap ----
#pragma unroll 1
    for (int k = 0; k < KT; ++k) {
        int cur = k & 1;
        uint32_t ab  = smb + (cur ? SM_A1 : SM_A0);
        uint32_t wbb = smb + (cur ? SM_W1 : SM_W0);
        char*  anx = sm + (cur ? SM_A0 : SM_A1);
        uint32_t wnx = smb + (cur ? SM_W0 : SM_W1);
        bool more = (k + 1 < KT);

        if (more) issue_w(wnx, g_wh16 + (k + 1) * 4096, g_wl16 + (k + 1) * 4096, tid);

        uint2 L[16];
        if (more) gather_load(xh, ca, k + 1, 0, q, sub, L);
        mma_two_ks(ab, wbb, 0, a_off, b_off, acc);
        if (more) gather_store(cwf, k + 1, 0, q, sub, L, anx);
        if (more) gather_load(xh, ca, k + 1, 4, q, sub, L);
        mma_two_ks(ab, wbb, 2, a_off, b_off, acc);
        if (more) gather_store(cwf, k + 1, 4, q, sub, L, anx);

        cp_async_wait_all();
        __syncthreads();
    }

    // ---- epilogue: bias + relu ----
    int obase = b * COUT * HW + row * WW;
#pragma unroll
    for (int mt = 0; mt < 2; ++mt) {
        int px = pxq * 32 + mt * 16 + (lane >> 2);
#pragma unroll
        for (int nt = 0; nt < 4; ++nt) {
            int oc = ocg2 * 32 + nt * 8 + (lane & 3) * 2;
            float b0 = __ldg(&g_bias2[oc]);
            float b1 = __ldg(&g_bias2[oc + 1]);
            out[obase + oc * HW + px]           = fmaxf(acc[mt][nt][0] + b0, 0.0f);
            out[obase + (oc + 1) * HW + px]     = fmaxf(acc[mt][nt][1] + b1, 0.0f);
            out[obase + oc * HW + px + 8]       = fmaxf(acc[mt][nt][2] + b0, 0.0f);
            out[obase + (oc + 1) * HW + px + 8] = fmaxf(acc[mt][nt][3] + b1, 0.0f);
        }
    }
}

// ---------------- launch ----------------
extern "C" void kernel_launch(void* const* d_in, const int* in_sizes, int n_in,
                              void* d_out, int out_size) {
    const float* x        = (const float*)d_in[0];
    const float* w_off    = (const float*)d_in[1];
    const float* b_off    = (const float*)d_in[2];
    const float* weight   = (const float*)d_in[3];
    const float* bias     = (const float*)d_in[4];
    const float* gamma    = (const float*)d_in[5];
    const float* beta     = (const float*)d_in[6];
    const float* run_mean = (const float*)d_in[7];
    const float* run_var  = (const float*)d_in[8];
    float* out = (float*)d_out;

    prep_kernel<<<(KT * CIN * COUT + 255) / 256, 256>>>(weight, bias, gamma, beta,
                                                        run_mean, run_var, w_off);

    transpose_kernel<<<BB * 2 * 512, 256>>>(x);

    cudaFuncSetAttribute(offset_mma_kernel,
                         cudaFuncAttributeMaxDynamicSharedMemorySize, OSM_TOTAL);
    offset_mma_kernel<<<BB * HH, 256, OSM_TOTAL>>>(b_off);

    cudaFuncSetAttribute(dcn_main_kernel,
                         cudaFuncAttributeMaxDynamicSharedMemorySize, SM_TOTAL);
    dcn_main_kernel<<<BB * HH, 256, SM_TOTAL>>>(out);
}